// round 13
// baseline (speedup 1.0000x reference)
#include <cuda_runtime.h>

// RNN: h_t = tanh(x_t * w_ih + b + W_hh @ h_{t-1}),  784 steps, H=30 (padded 32), B=8192
// out = h_T @ W_fc^T + b_fc   [8192, 10]
//
// Mapping: half-warp (16 lanes) owns one batch element; lane r computes rows 2r, 2r+1.
// W_hh row-pair held in 64 registers as f32x2 pairs (j-packed). Inner loop per step:
// 16 broadcast LDS.64 (h pairs) + 32 fma.rn.f32x2 => 1:2 LDS:FMA, matching SM capacities.

#define T_STEPS 784
#define HDIM 30

typedef unsigned long long u64;

__device__ __forceinline__ u64 pack2(float lo, float hi) {
    u64 r; asm("mov.b64 %0, {%1, %2};" : "=l"(r) : "f"(lo), "f"(hi)); return r;
}
__device__ __forceinline__ void unpack2(u64 v, float& lo, float& hi) {
    asm("mov.b64 {%0, %1}, %2;" : "=f"(lo), "=f"(hi) : "l"(v));
}
__device__ __forceinline__ void ffma2(u64& d, u64 a, u64 b) {
    asm("fma.rn.f32x2 %0, %1, %2, %0;" : "+l"(d) : "l"(a), "l"(b));
}
// tanh(x) = 1 - 2/(exp(2x)+1), via MUFU ex2/rcp. ~1e-6 error, saturates correctly at +-inf.
__device__ __forceinline__ float tanh_fast(float x) {
    float e, r;
    asm("ex2.approx.f32 %0, %1;" : "=f"(e) : "f"(x * 2.8853900817779268f)); // 2*log2(e)
    asm("rcp.approx.f32 %0, %1;" : "=f"(r) : "f"(e + 1.0f));
    return fmaf(-2.0f, r, 1.0f);
}

__global__ void __launch_bounds__(256) rnn_kernel(
    const float* __restrict__ x,     // [B, T]  (I==1)
    const float* __restrict__ W_ih,  // [30]
    const float* __restrict__ W_hh,  // [30,30]
    const float* __restrict__ b_ih,  // [30]
    const float* __restrict__ b_hh,  // [30]
    const float* __restrict__ W_fc,  // [10,30]
    const float* __restrict__ b_fc,  // [10]
    float* __restrict__ out)         // [B,10]
{
    __shared__ float Wsh[32][32];     // zero-padded W_hh
    __shared__ float wihs[32], biass[32];
    __shared__ u64 hbuf[8][2][2][16]; // [warp][pingpong][elem-half][h pair]

    const int tid = threadIdx.x;

    // Stage weights into shared (zero-padded to 32x32)
    for (int i = tid; i < 1024; i += 256) ((float*)Wsh)[i] = 0.0f;
    if (tid < 32) { wihs[tid] = 0.0f; biass[tid] = 0.0f; }
    __syncthreads();
    for (int i = tid; i < HDIM * HDIM; i += 256) Wsh[i / HDIM][i % HDIM] = W_hh[i];
    if (tid < HDIM) { wihs[tid] = W_ih[tid]; biass[tid] = b_ih[tid] + b_hh[tid]; }
    __syncthreads();

    const int w    = tid >> 5;
    const int half = (tid >> 4) & 1;
    const int r    = tid & 15;       // row pair index (rows 2r, 2r+1)
    const int elem = blockIdx.x * 16 + w * 2 + half;

    // W_hh row pair -> 32 f32x2 register pairs (64 regs).
    // W0[jp] = (W[2r][2jp], W[2r][2jp+1]) ; W1 same for row 2r+1.
    u64 W0[16], W1[16];
#pragma unroll
    for (int jp = 0; jp < 16; jp++) {
        W0[jp] = pack2(Wsh[2 * r][2 * jp], Wsh[2 * r][2 * jp + 1]);
        W1[jp] = pack2(Wsh[2 * r + 1][2 * jp], Wsh[2 * r + 1][2 * jp + 1]);
    }
    const float wih0 = wihs[2 * r],  wih1 = wihs[2 * r + 1];
    const float bi0  = biass[2 * r], bi1  = biass[2 * r + 1];

    u64* hc = &hbuf[w][0][half][0];
    u64* hn = &hbuf[w][1][half][0];
    hc[r] = 0ull;                    // h0 = 0 (rows 30,31 stay 0 forever: wih/bias/W padded 0)
    __syncwarp();

    const float* xg = x + (long long)elem * T_STEPS;

    for (int tb = 0; tb < T_STEPS; tb += 16) {
        // stage 16 timesteps of x for this element across the half-warp lanes
        float xs = xg[tb + r];
#pragma unroll 4
        for (int tt = 0; tt < 16; tt++) {
            float xv = __shfl_sync(0xffffffffu, xs, tt, 16);  // broadcast within half-warp
            // accumulators: (even-j partial, odd-j partial) per row; bias + x*w_ih folded in
            u64 a0a = pack2(fmaf(xv, wih0, bi0), 0.0f);
            u64 a1a = pack2(fmaf(xv, wih1, bi1), 0.0f);
            u64 a0b = 0ull, a1b = 0ull;
#pragma unroll
            for (int jp = 0; jp < 16; jp += 2) {
                u64 h0 = hc[jp];       // LDS.64, broadcast across the 16 lanes of this half
                u64 h1 = hc[jp + 1];
                ffma2(a0a, W0[jp],     h0);
                ffma2(a1a, W1[jp],     h0);
                ffma2(a0b, W0[jp + 1], h1);
                ffma2(a1b, W1[jp + 1], h1);
            }
            float p, q, s, t2;
            unpack2(a0a, p, q); unpack2(a0b, s, t2);
            const float s0 = (p + q) + (s + t2);
            unpack2(a1a, p, q); unpack2(a1b, s, t2);
            const float s1 = (p + q) + (s + t2);
            hn[r] = pack2(tanh_fast(s0), tanh_fast(s1));
            __syncwarp();
            u64* tmp = hc; hc = hn; hn = tmp;
        }
    }

    // FC head: lanes r<10 of each half-warp compute one output class each
    if (r < 10) {
        float acc = b_fc[r];
#pragma unroll
        for (int jp = 0; jp < 15; jp++) {
            float lo, hi; unpack2(hc[jp], lo, hi);
            acc = fmaf(lo, W_fc[r * HDIM + 2 * jp],     acc);
            acc = fmaf(hi, W_fc[r * HDIM + 2 * jp + 1], acc);
        }
        out[elem * 10 + r] = acc;
    }
}

extern "C" void kernel_launch(void* const* d_in, const int* in_sizes, int n_in,
                              void* d_out, int out_size) {
    const float* x    = (const float*)d_in[0];
    const float* W_ih = (const float*)d_in[1];
    const float* W_hh = (const float*)d_in[2];
    const float* b_ih = (const float*)d_in[3];
    const float* b_hh = (const float*)d_in[4];
    const float* W_fc = (const float*)d_in[5];
    const float* b_fc = (const float*)d_in[6];
    float* out = (float*)d_out;

    // 8192 elems / 16 per CTA (8 warps x 2 elems per warp)
    rnn_kernel<<<512, 256>>>(x, W_ih, W_hh, b_ih, b_hh, W_fc, b_fc, out);
}

// round 14
// speedup vs baseline: 1.0018x; 1.0018x over previous
#include <cuda_runtime.h>

// RNN: h_t = tanh(x_t * w_ih + b + W_hh @ h_{t-1}),  784 steps, H=30 (padded 32), B=8192
// out = h_T @ W_fc^T + b_fc   [8192, 10]
//
// Mapping: half-warp (16 lanes) owns one batch element; lane r computes rows 2r, 2r+1.
// W_hh row-pair held in 64 registers as f32x2 pairs (j-packed). Inner loop per step:
// 16 broadcast LDS.64 (h pairs) + 32 fma.rn.f32x2 => 1:2 LDS:FMA, matching SM capacities.

#define T_STEPS 784
#define HDIM 30

typedef unsigned long long u64;

__device__ __forceinline__ u64 pack2(float lo, float hi) {
    u64 r; asm("mov.b64 %0, {%1, %2};" : "=l"(r) : "f"(lo), "f"(hi)); return r;
}
__device__ __forceinline__ void unpack2(u64 v, float& lo, float& hi) {
    asm("mov.b64 {%0, %1}, %2;" : "=f"(lo), "=f"(hi) : "l"(v));
}
__device__ __forceinline__ void ffma2(u64& d, u64 a, u64 b) {
    asm("fma.rn.f32x2 %0, %1, %2, %0;" : "+l"(d) : "l"(a), "l"(b));
}
// tanh(x) = 1 - 2/(exp(2x)+1), via MUFU ex2/rcp. ~1e-6 error, saturates correctly at +-inf.
__device__ __forceinline__ float tanh_fast(float x) {
    float e, r;
    asm("ex2.approx.f32 %0, %1;" : "=f"(e) : "f"(x * 2.8853900817779268f)); // 2*log2(e)
    asm("rcp.approx.f32 %0, %1;" : "=f"(r) : "f"(e + 1.0f));
    return fmaf(-2.0f, r, 1.0f);
}

__global__ void __launch_bounds__(256) rnn_kernel(
    const float* __restrict__ x,     // [B, T]  (I==1)
    const float* __restrict__ W_ih,  // [30]
    const float* __restrict__ W_hh,  // [30,30]
    const float* __restrict__ b_ih,  // [30]
    const float* __restrict__ b_hh,  // [30]
    const float* __restrict__ W_fc,  // [10,30]
    const float* __restrict__ b_fc,  // [10]
    float* __restrict__ out)         // [B,10]
{
    __shared__ float Wsh[32][32];     // zero-padded W_hh
    __shared__ float wihs[32], biass[32];
    __shared__ u64 hbuf[8][2][2][16]; // [warp][pingpong][elem-half][h pair]

    const int tid = threadIdx.x;

    // Stage weights into shared (zero-padded to 32x32)
    for (int i = tid; i < 1024; i += 256) ((float*)Wsh)[i] = 0.0f;
    if (tid < 32) { wihs[tid] = 0.0f; biass[tid] = 0.0f; }
    __syncthreads();
    for (int i = tid; i < HDIM * HDIM; i += 256) Wsh[i / HDIM][i % HDIM] = W_hh[i];
    if (tid < HDIM) { wihs[tid] = W_ih[tid]; biass[tid] = b_ih[tid] + b_hh[tid]; }
    __syncthreads();

    const int w    = tid >> 5;
    const int half = (tid >> 4) & 1;
    const int r    = tid & 15;       // row pair index (rows 2r, 2r+1)
    const int elem = blockIdx.x * 16 + w * 2 + half;

    // W_hh row pair -> 32 f32x2 register pairs (64 regs).
    // W0[jp] = (W[2r][2jp], W[2r][2jp+1]) ; W1 same for row 2r+1.
    u64 W0[16], W1[16];
#pragma unroll
    for (int jp = 0; jp < 16; jp++) {
        W0[jp] = pack2(Wsh[2 * r][2 * jp], Wsh[2 * r][2 * jp + 1]);
        W1[jp] = pack2(Wsh[2 * r + 1][2 * jp], Wsh[2 * r + 1][2 * jp + 1]);
    }
    const float wih0 = wihs[2 * r],  wih1 = wihs[2 * r + 1];
    const float bi0  = biass[2 * r], bi1  = biass[2 * r + 1];

    u64* hc = &hbuf[w][0][half][0];
    u64* hn = &hbuf[w][1][half][0];
    hc[r] = 0ull;                    // h0 = 0 (rows 30,31 stay 0 forever: wih/bias/W padded 0)
    __syncwarp();

    const float* xg = x + (long long)elem * T_STEPS;

    for (int tb = 0; tb < T_STEPS; tb += 16) {
        // stage 16 timesteps of x for this element across the half-warp lanes
        float xs = xg[tb + r];
#pragma unroll 4
        for (int tt = 0; tt < 16; tt++) {
            float xv = __shfl_sync(0xffffffffu, xs, tt, 16);  // broadcast within half-warp
            // accumulators: (even-j partial, odd-j partial) per row; bias + x*w_ih folded in
            u64 a0a = pack2(fmaf(xv, wih0, bi0), 0.0f);
            u64 a1a = pack2(fmaf(xv, wih1, bi1), 0.0f);
            u64 a0b = 0ull, a1b = 0ull;
#pragma unroll
            for (int jp = 0; jp < 16; jp += 2) {
                u64 h0 = hc[jp];       // LDS.64, broadcast across the 16 lanes of this half
                u64 h1 = hc[jp + 1];
                ffma2(a0a, W0[jp],     h0);
                ffma2(a1a, W1[jp],     h0);
                ffma2(a0b, W0[jp + 1], h1);
                ffma2(a1b, W1[jp + 1], h1);
            }
            float p, q, s, t2;
            unpack2(a0a, p, q); unpack2(a0b, s, t2);
            const float s0 = (p + q) + (s + t2);
            unpack2(a1a, p, q); unpack2(a1b, s, t2);
            const float s1 = (p + q) + (s + t2);
            hn[r] = pack2(tanh_fast(s0), tanh_fast(s1));
            __syncwarp();
            u64* tmp = hc; hc = hn; hn = tmp;
        }
    }

    // FC head: lanes r<10 of each half-warp compute one output class each
    if (r < 10) {
        float acc = b_fc[r];
#pragma unroll
        for (int jp = 0; jp < 15; jp++) {
            float lo, hi; unpack2(hc[jp], lo, hi);
            acc = fmaf(lo, W_fc[r * HDIM + 2 * jp],     acc);
            acc = fmaf(hi, W_fc[r * HDIM + 2 * jp + 1], acc);
        }
        out[elem * 10 + r] = acc;
    }
}

extern "C" void kernel_launch(void* const* d_in, const int* in_sizes, int n_in,
                              void* d_out, int out_size) {
    const float* x    = (const float*)d_in[0];
    const float* W_ih = (const float*)d_in[1];
    const float* W_hh = (const float*)d_in[2];
    const float* b_ih = (const float*)d_in[3];
    const float* b_hh = (const float*)d_in[4];
    const float* W_fc = (const float*)d_in[5];
    const float* b_fc = (const float*)d_in[6];
    float* out = (float*)d_out;

    // 8192 elems / 16 per CTA (8 warps x 2 elems per warp)
    rnn_kernel<<<512, 256>>>(x, W_ih, W_hh, b_ih, b_hh, W_fc, b_fc, out);
}